// round 10
// baseline (speedup 1.0000x reference)
#include <cuda_runtime.h>
#include <cuda_bf16.h>

// InverseLeakySoftplus: solve a*x + (1-a)*softplus(x) = y, a = 0.1+0.4*sigmoid(raw_alpha).
//
// R9 post-mortem: kernel is DRAM-LATENCY-bound at the Little's-law knee
// (~105 outstanding LDG.128/SM needed; R7/R9 both ~60% effective). Neither
// occupancy alone (R9) nor IPT alone (R7) sufficed. R10: maximize the
// product -> 48 warps/SM x IPT=4 = 192 nominal outstanding loads.
// Table: x-only, h=0.01 (12.8KB, 6 blocks/SM fits carveout), lerp with
// adjacent-pair LDS (ptxas merges to LDS.64). rel_err 1.157e-6 (validated).

#define NSEG  3200
#define YMINF (-16.0f)
#define H_F   0.01f
#define INVH  100.0f
#define TOFF  1600.0f          // -YMIN/h
#define TPB   256
#define IPT   4                // float4 per thread per grid-stride step
#define NBLOCKS 912            // 152 SMs x 6 blocks (48 warps/SM)

__device__ float g_tab[NSEG + 1];   // x(y_k)
__device__ float g_inva;

// ---------- table builder ----------
__device__ __forceinline__ float solve_knot(float y, float a, float oma, float inva)
{
    float x = (y > 0.0f) ? y : y * inva;
#pragma unroll
    for (int it = 0; it < 7; ++it) {
        float e  = __expf(-fabsf(x));
        float op = 1.0f + e;
        float sp = __logf(op) + fmaxf(x, 0.0f);
        float fx = fmaf(a, x, oma * sp);
        float num = (x >= 0.0f) ? fmaf(a, e, 1.0f) : (a + e);
        x -= __fdividef((fx - y) * op, num);
    }
    return x;
}

__global__ void build_table(const float* __restrict__ raw_alpha)
{
    int k = blockIdx.x * blockDim.x + threadIdx.x;
    float r    = __ldg(raw_alpha);
    float sig  = __fdividef(1.0f, 1.0f + __expf(-r));
    float a    = fmaf(0.4f, sig, 0.1f);
    float oma  = 1.0f - a;
    float inva = __fdividef(1.0f, a);
    if (k == 0) g_inva = inva;
    if (k <= NSEG) {
        g_tab[k] = solve_knot(YMINF + (float)k * H_F, a, oma, inva);
    }
}

// ---------- main: lerp from x-only table, zero MUFU ----------
__device__ __forceinline__ float lerp_solve(float y, float inva,
                                            const float* __restrict__ s_tab)
{
    float t = fmaf(y, INVH, TOFF);
    t = fminf(fmaxf(t, 0.0f), (float)NSEG - 0.001f);
    int   k  = (int)t;
    float fr = t - (float)k;
    float x0 = s_tab[k];
    float x1 = s_tab[k + 1];
    float x  = fmaf(fr, x1 - x0, x0);
    x = (y >=  16.0f) ? y        : x;
    x = (y <= -16.0f) ? y * inva : x;
    return x;
}

__global__ void __launch_bounds__(TPB, 6)
inv_lsp_main(const float4* __restrict__ in, float4* __restrict__ out, int n4)
{
    __shared__ float s_tab[NSEG + 1];
    for (int j = threadIdx.x; j < NSEG + 1; j += TPB) s_tab[j] = g_tab[j];
    float inva = g_inva;
    __syncthreads();

    int tid     = blockIdx.x * TPB + threadIdx.x;
    int gstride = gridDim.x * TPB;           // 233,472
    int step    = gstride * IPT;

    for (int i0 = tid; i0 < n4; i0 += step) {
        float4 v[IPT];
        int    ok[IPT];
#pragma unroll
        for (int j = 0; j < IPT; ++j) {      // front-batched loads (MLP=4)
            int i = i0 + j * gstride;
            ok[j] = (i < n4);
            if (ok[j]) v[j] = in[i];
        }
#pragma unroll
        for (int j = 0; j < IPT; ++j) {
            if (ok[j]) {
                float4 rr;
                rr.x = lerp_solve(v[j].x, inva, s_tab);
                rr.y = lerp_solve(v[j].y, inva, s_tab);
                rr.z = lerp_solve(v[j].z, inva, s_tab);
                rr.w = lerp_solve(v[j].w, inva, s_tab);
                out[i0 + j * gstride] = rr;
            }
        }
    }
}

// ---------- scalar tail (safety; unused when n % 4 == 0) ----------
__global__ void inv_lsp_scalar_tail(const float* __restrict__ in,
                                    float* __restrict__ out,
                                    int start, int n)
{
    int i = start + blockIdx.x * blockDim.x + threadIdx.x;
    if (i >= n) return;
    float inva = g_inva;
    float a    = __fdividef(1.0f, inva);
    float oma  = 1.0f - a;
    float y = in[i];
    float x = (y > 0.0f) ? y : y * inva;
#pragma unroll
    for (int it = 0; it < 8; ++it) {
        float e  = __expf(-fabsf(x));
        float op = 1.0f + e;
        float sp = __logf(op) + fmaxf(x, 0.0f);
        float fx = fmaf(a, x, oma * sp);
        float num = (x >= 0.0f) ? fmaf(a, e, 1.0f) : (a + e);
        x -= __fdividef((fx - y) * op, num);
    }
    out[i] = x;
}

extern "C" void kernel_launch(void* const* d_in, const int* in_sizes, int n_in,
                              void* d_out, int out_size)
{
    const float* in        = (const float*)d_in[0];
    const float* raw_alpha = (const float*)d_in[1];
    float* out             = (float*)d_out;
    int n = in_sizes[0];

    // Host-side, idempotent, capture-safe (no alloc, no stream op).
    static int carveout_set = 0;
    if (!carveout_set) {
        cudaFuncSetAttribute(inv_lsp_main,
                             cudaFuncAttributePreferredSharedMemoryCarveout,
                             (int)cudaSharedmemCarveoutMaxShared);
        carveout_set = 1;
    }

    build_table<<<(NSEG + 128) / 128, 128>>>(raw_alpha);

    int n4 = n / 4;
    if (n4 > 0) {
        int blocks = NBLOCKS;
        int needed = (n4 + TPB - 1) / TPB;
        if (needed < blocks) blocks = needed;
        inv_lsp_main<<<blocks, TPB>>>((const float4*)in, (float4*)out, n4);
    }
    int rem = n - n4 * 4;
    if (rem > 0) {
        inv_lsp_scalar_tail<<<1, 256>>>(in, out, n4 * 4, n);
    }
}

// round 11
// speedup vs baseline: 1.0193x; 1.0193x over previous
#include <cuda_runtime.h>
#include <cuda_bf16.h>

// InverseLeakySoftplus: solve a*x + (1-a)*softplus(x) = y, a = 0.1+0.4*sigmoid(raw_alpha).
//
// R10 post-mortem: the x-only table (R9/R10) emits TWO LDS.32 per element
// (ptxas can't prove 8B alignment to merge) -> +12 LSU cyc per float4-warp
// -> +~11us vs R7's float2/LDS.64 table. LSU/MIO is the co-binder with DRAM;
// occupancy was a red herring (DRAM stuck 52-58% across 30/48/52 warps).
// R11 = R7 inner loop (float2 {x,dx} table, h=0.01, one LDS.64/elem)
//      + 48 warps/SM (6 blocks x 256, max-shared carveout: 6x25.6KB=154KB)
//      + __ldcs/__stcs streaming hints (no-reuse streams, evict-first).

#define NSEG  3200
#define YMINF (-16.0f)
#define H_F   0.01f
#define INVH  100.0f
#define TOFF  1600.0f          // -YMIN/h
#define TPB   256
#define IPT   4                // float4 per thread per grid-stride step
#define NBLOCKS 912            // 152 SMs x 6 blocks (48 warps/SM)

__device__ float2 g_tab[NSEG]; // {x_k, x_{k+1}-x_k}
__device__ float  g_inva;

// ---------- table builder ----------
__device__ __forceinline__ float solve_knot(float y, float a, float oma, float inva)
{
    float x = (y > 0.0f) ? y : y * inva;
#pragma unroll
    for (int it = 0; it < 7; ++it) {
        float e  = __expf(-fabsf(x));
        float op = 1.0f + e;
        float sp = __logf(op) + fmaxf(x, 0.0f);
        float fx = fmaf(a, x, oma * sp);
        float num = (x >= 0.0f) ? fmaf(a, e, 1.0f) : (a + e);
        x -= __fdividef((fx - y) * op, num);
    }
    return x;
}

__global__ void build_table(const float* __restrict__ raw_alpha)
{
    int k = blockIdx.x * blockDim.x + threadIdx.x;
    float r    = __ldg(raw_alpha);
    float sig  = __fdividef(1.0f, 1.0f + __expf(-r));
    float a    = fmaf(0.4f, sig, 0.1f);
    float oma  = 1.0f - a;
    float inva = __fdividef(1.0f, a);
    if (k == 0) g_inva = inva;
    if (k < NSEG) {
        float y0 = YMINF + (float)k * H_F;
        float x0 = solve_knot(y0, a, oma, inva);
        float x1 = solve_knot(y0 + H_F, a, oma, inva);
        g_tab[k] = make_float2(x0, x1 - x0);
    }
}

// ---------- main: lerp, one LDS.64 per element, zero MUFU ----------
__device__ __forceinline__ float lerp_solve(float y, float inva,
                                            const float2* __restrict__ s_tab)
{
    float t = fmaf(y, INVH, TOFF);
    t = fminf(fmaxf(t, 0.0f), (float)NSEG - 0.001f);
    int   k  = (int)t;
    float fr = t - (float)k;
    float2 p = s_tab[k];
    float x  = fmaf(fr, p.y, p.x);
    x = (y >=  16.0f) ? y        : x;
    x = (y <= -16.0f) ? y * inva : x;
    return x;
}

__global__ void __launch_bounds__(TPB, 6)
inv_lsp_main(const float4* __restrict__ in, float4* __restrict__ out, int n4)
{
    __shared__ float2 s_tab[NSEG];
    for (int j = threadIdx.x; j < NSEG; j += TPB) s_tab[j] = g_tab[j];
    float inva = g_inva;
    __syncthreads();

    int tid     = blockIdx.x * TPB + threadIdx.x;
    int gstride = gridDim.x * TPB;           // 233,472
    int step    = gstride * IPT;

    for (int i0 = tid; i0 < n4; i0 += step) {
        float4 v[IPT];
        int    ok[IPT];
#pragma unroll
        for (int j = 0; j < IPT; ++j) {      // front-batched loads (MLP=4)
            int i = i0 + j * gstride;
            ok[j] = (i < n4);
            if (ok[j]) v[j] = __ldcs(&in[i]);   // streaming: evict-first
        }
#pragma unroll
        for (int j = 0; j < IPT; ++j) {
            if (ok[j]) {
                float4 rr;
                rr.x = lerp_solve(v[j].x, inva, s_tab);
                rr.y = lerp_solve(v[j].y, inva, s_tab);
                rr.z = lerp_solve(v[j].z, inva, s_tab);
                rr.w = lerp_solve(v[j].w, inva, s_tab);
                __stcs(&out[i0 + j * gstride], rr);  // streaming store
            }
        }
    }
}

// ---------- scalar tail (safety; unused when n % 4 == 0) ----------
__global__ void inv_lsp_scalar_tail(const float* __restrict__ in,
                                    float* __restrict__ out,
                                    int start, int n)
{
    int i = start + blockIdx.x * blockDim.x + threadIdx.x;
    if (i >= n) return;
    float inva = g_inva;
    float a    = __fdividef(1.0f, inva);
    float oma  = 1.0f - a;
    float y = in[i];
    float x = (y > 0.0f) ? y : y * inva;
#pragma unroll
    for (int it = 0; it < 8; ++it) {
        float e  = __expf(-fabsf(x));
        float op = 1.0f + e;
        float sp = __logf(op) + fmaxf(x, 0.0f);
        float fx = fmaf(a, x, oma * sp);
        float num = (x >= 0.0f) ? fmaf(a, e, 1.0f) : (a + e);
        x -= __fdividef((fx - y) * op, num);
    }
    out[i] = x;
}

extern "C" void kernel_launch(void* const* d_in, const int* in_sizes, int n_in,
                              void* d_out, int out_size)
{
    const float* in        = (const float*)d_in[0];
    const float* raw_alpha = (const float*)d_in[1];
    float* out             = (float*)d_out;
    int n = in_sizes[0];

    // Host-side, idempotent, capture-safe (no alloc, no stream op).
    static int carveout_set = 0;
    if (!carveout_set) {
        cudaFuncSetAttribute(inv_lsp_main,
                             cudaFuncAttributePreferredSharedMemoryCarveout,
                             (int)cudaSharedmemCarveoutMaxShared);
        carveout_set = 1;
    }

    build_table<<<(NSEG + 127) / 128, 128>>>(raw_alpha);

    int n4 = n / 4;
    if (n4 > 0) {
        int blocks = NBLOCKS;
        int needed = (n4 + TPB - 1) / TPB;
        if (needed < blocks) blocks = needed;
        inv_lsp_main<<<blocks, TPB>>>((const float4*)in, (float4*)out, n4);
    }
    int rem = n - n4 * 4;
    if (rem > 0) {
        inv_lsp_scalar_tail<<<1, 256>>>(in, out, n4 * 4, n);
    }
}

// round 12
// speedup vs baseline: 1.0434x; 1.0237x over previous
#include <cuda_runtime.h>
#include <cuda_bf16.h>

// InverseLeakySoftplus: solve a*x + (1-a)*softplus(x) = y, a = 0.1+0.4*sigmoid(raw_alpha).
//
// R11 post-mortem: across R7..R11 the ONLY fast config (46.8us main, DRAM 58%)
// is R7, and its unique property is LONG LONG index math -> ptxas computes the
// IPT load addresses independently (IMAD.WIDE) and front-batches all LDG.128s
// (MLP_p1=IPT). The int-indexed variants strength-reduce into dependent
// address chains, interleaving loads with compute -> effective MLP halved,
// DRAM stuck ~51%. R12 = exact R7 structure (long long, float2 h=0.01 table,
// 608 blocks, bounds(256,4)) with IPT=8 to double the front-batched run.

#define NSEG  3200
#define YMINF (-16.0f)
#define H_F   0.01f
#define INVH  100.0f
#define TOFF  1600.0f          // -YMIN/h
#define TPB   256
#define IPT   8                // float4 per thread per grid-stride step
#define NBLOCKS 608            // 152 SMs x 4 blocks

__device__ float2 g_tab[NSEG];  // {x_k, x_{k+1}-x_k}
__device__ float  g_inva;

// ---------- table builder ----------
__device__ __forceinline__ float solve_knot(float y, float a, float oma, float inva)
{
    float x = (y > 0.0f) ? y : y * inva;
#pragma unroll
    for (int it = 0; it < 7; ++it) {
        float e  = __expf(-fabsf(x));
        float op = 1.0f + e;
        float sp = __logf(op) + fmaxf(x, 0.0f);
        float fx = fmaf(a, x, oma * sp);
        float num = (x >= 0.0f) ? fmaf(a, e, 1.0f) : (a + e);
        x -= __fdividef((fx - y) * op, num);
    }
    return x;
}

__global__ void build_table(const float* __restrict__ raw_alpha)
{
    int k = blockIdx.x * blockDim.x + threadIdx.x;
    float r    = __ldg(raw_alpha);
    float sig  = __fdividef(1.0f, 1.0f + __expf(-r));
    float a    = fmaf(0.4f, sig, 0.1f);
    float oma  = 1.0f - a;
    float inva = __fdividef(1.0f, a);
    if (k == 0) g_inva = inva;
    if (k < NSEG) {
        float y0 = YMINF + (float)k * H_F;
        float x0 = solve_knot(y0, a, oma, inva);
        float x1 = solve_knot(y0 + H_F, a, oma, inva);
        g_tab[k] = make_float2(x0, x1 - x0);
    }
}

// ---------- main: lerp, one LDS.64 per element, zero MUFU ----------
__device__ __forceinline__ float lerp_solve(float y, float inva,
                                            const float2* __restrict__ s_tab)
{
    float t = fmaf(y, INVH, TOFF);
    t = fminf(fmaxf(t, 0.0f), (float)NSEG - 0.001f);
    int   k  = (int)t;
    float fr = t - (float)k;
    float2 p = s_tab[k];
    float x  = fmaf(fr, p.y, p.x);
    x = (y >=  16.0f) ? y        : x;
    x = (y <= -16.0f) ? y * inva : x;
    return x;
}

__global__ void __launch_bounds__(TPB, 4)
inv_lsp_main(const float4* __restrict__ in, float4* __restrict__ out, int n4)
{
    __shared__ float2 s_tab[NSEG];
    for (int j = threadIdx.x; j < NSEG; j += TPB) s_tab[j] = g_tab[j];
    float inva = g_inva;
    __syncthreads();

    int tid     = blockIdx.x * TPB + threadIdx.x;
    int gstride = gridDim.x * TPB;
    long long step = (long long)gstride * IPT;

    for (long long i0 = tid; i0 < n4; i0 += step) {
        float4 v[IPT];
        int    ok[IPT];
#pragma unroll
        for (int j = 0; j < IPT; ++j) {          // front-batched loads (MLP=IPT)
            long long i = i0 + (long long)j * gstride;
            ok[j] = (i < n4);
            if (ok[j]) v[j] = in[i];
        }
#pragma unroll
        for (int j = 0; j < IPT; ++j) {
            if (ok[j]) {
                float4 rr;
                rr.x = lerp_solve(v[j].x, inva, s_tab);
                rr.y = lerp_solve(v[j].y, inva, s_tab);
                rr.z = lerp_solve(v[j].z, inva, s_tab);
                rr.w = lerp_solve(v[j].w, inva, s_tab);
                out[i0 + (long long)j * gstride] = rr;
            }
        }
    }
}

// ---------- scalar tail (safety; unused when n % 4 == 0) ----------
__global__ void inv_lsp_scalar_tail(const float* __restrict__ in,
                                    float* __restrict__ out,
                                    int start, int n)
{
    int i = start + blockIdx.x * blockDim.x + threadIdx.x;
    if (i >= n) return;
    float inva = g_inva;
    float a    = __fdividef(1.0f, inva);
    float oma  = 1.0f - a;
    float y = in[i];
    float x = (y > 0.0f) ? y : y * inva;
#pragma unroll
    for (int it = 0; it < 8; ++it) {
        float e  = __expf(-fabsf(x));
        float op = 1.0f + e;
        float sp = __logf(op) + fmaxf(x, 0.0f);
        float fx = fmaf(a, x, oma * sp);
        float num = (x >= 0.0f) ? fmaf(a, e, 1.0f) : (a + e);
        x -= __fdividef((fx - y) * op, num);
    }
    out[i] = x;
}

extern "C" void kernel_launch(void* const* d_in, const int* in_sizes, int n_in,
                              void* d_out, int out_size)
{
    const float* in        = (const float*)d_in[0];
    const float* raw_alpha = (const float*)d_in[1];
    float* out             = (float*)d_out;
    int n = in_sizes[0];

    build_table<<<(NSEG + 127) / 128, 128>>>(raw_alpha);

    int n4 = n / 4;
    if (n4 > 0) {
        int blocks = NBLOCKS;
        int needed = (n4 + TPB - 1) / TPB;
        if (needed < blocks) blocks = needed;
        inv_lsp_main<<<blocks, TPB>>>((const float4*)in, (float4*)out, n4);
    }
    int rem = n - n4 * 4;
    if (rem > 0) {
        inv_lsp_scalar_tail<<<1, 256>>>(in, out, n4 * 4, n);
    }
}

// round 13
// speedup vs baseline: 1.0687x; 1.0242x over previous
#include <cuda_runtime.h>
#include <cuda_bf16.h>

// InverseLeakySoftplus: solve a*x + (1-a)*softplus(x) = y, a = 0.1+0.4*sigmoid(raw_alpha).
//
// R12 post-mortem: long-long front-batched loads confirmed as the DRAM%
// lever (58-59% only in those configs). Main at 45.7us vs ~34us floor.
// R13 single-variable test: __ldcs/__stcs streaming policy on the frozen R12
// skeleton. Theory: default write-allocate puts 128MB of store lines in L2,
// evicting in-flight read sectors -> DRAM caps at 59%. Evict-first on both
// streams should lift DRAM toward 70%+. If neutral, L2 policy is exonerated
// and the residual is fixed overhead + latency ramp.

#define NSEG  3200
#define YMINF (-16.0f)
#define H_F   0.01f
#define INVH  100.0f
#define TOFF  1600.0f          // -YMIN/h
#define TPB   256
#define IPT   8                // float4 per thread per grid-stride step
#define NBLOCKS 608            // 152 SMs x 4 blocks

__device__ float2 g_tab[NSEG];  // {x_k, x_{k+1}-x_k}
__device__ float  g_inva;

// ---------- table builder ----------
__device__ __forceinline__ float solve_knot(float y, float a, float oma, float inva)
{
    float x = (y > 0.0f) ? y : y * inva;
#pragma unroll
    for (int it = 0; it < 6; ++it) {     // knot err ~1e-7 (R2 trace: 4 iters suffice)
        float e  = __expf(-fabsf(x));
        float op = 1.0f + e;
        float sp = __logf(op) + fmaxf(x, 0.0f);
        float fx = fmaf(a, x, oma * sp);
        float num = (x >= 0.0f) ? fmaf(a, e, 1.0f) : (a + e);
        x -= __fdividef((fx - y) * op, num);
    }
    return x;
}

__global__ void build_table(const float* __restrict__ raw_alpha)
{
    int k = blockIdx.x * blockDim.x + threadIdx.x;
    float r    = __ldg(raw_alpha);
    float sig  = __fdividef(1.0f, 1.0f + __expf(-r));
    float a    = fmaf(0.4f, sig, 0.1f);
    float oma  = 1.0f - a;
    float inva = __fdividef(1.0f, a);
    if (k == 0) g_inva = inva;
    if (k < NSEG) {
        float y0 = YMINF + (float)k * H_F;
        float x0 = solve_knot(y0, a, oma, inva);
        float x1 = solve_knot(y0 + H_F, a, oma, inva);
        g_tab[k] = make_float2(x0, x1 - x0);
    }
}

// ---------- main: lerp, one LDS.64 per element, zero MUFU ----------
__device__ __forceinline__ float lerp_solve(float y, float inva,
                                            const float2* __restrict__ s_tab)
{
    float t = fmaf(y, INVH, TOFF);
    t = fminf(fmaxf(t, 0.0f), (float)NSEG - 0.001f);
    int   k  = (int)t;
    float fr = t - (float)k;
    float2 p = s_tab[k];
    float x  = fmaf(fr, p.y, p.x);
    x = (y >=  16.0f) ? y        : x;
    x = (y <= -16.0f) ? y * inva : x;
    return x;
}

__global__ void __launch_bounds__(TPB, 4)
inv_lsp_main(const float4* __restrict__ in, float4* __restrict__ out, int n4)
{
    __shared__ float2 s_tab[NSEG];
    for (int j = threadIdx.x; j < NSEG; j += TPB) s_tab[j] = g_tab[j];
    float inva = g_inva;
    __syncthreads();

    int tid     = blockIdx.x * TPB + threadIdx.x;
    int gstride = gridDim.x * TPB;
    long long step = (long long)gstride * IPT;

    for (long long i0 = tid; i0 < n4; i0 += step) {
        float4 v[IPT];
        int    ok[IPT];
#pragma unroll
        for (int j = 0; j < IPT; ++j) {          // front-batched loads (MLP=IPT)
            long long i = i0 + (long long)j * gstride;
            ok[j] = (i < n4);
            if (ok[j]) v[j] = __ldcs(&in[i]);    // streaming read: evict-first
        }
#pragma unroll
        for (int j = 0; j < IPT; ++j) {
            if (ok[j]) {
                float4 rr;
                rr.x = lerp_solve(v[j].x, inva, s_tab);
                rr.y = lerp_solve(v[j].y, inva, s_tab);
                rr.z = lerp_solve(v[j].z, inva, s_tab);
                rr.w = lerp_solve(v[j].w, inva, s_tab);
                __stcs(&out[i0 + (long long)j * gstride], rr);  // streaming store
            }
        }
    }
}

// ---------- scalar tail (safety; unused when n % 4 == 0) ----------
__global__ void inv_lsp_scalar_tail(const float* __restrict__ in,
                                    float* __restrict__ out,
                                    int start, int n)
{
    int i = start + blockIdx.x * blockDim.x + threadIdx.x;
    if (i >= n) return;
    float inva = g_inva;
    float a    = __fdividef(1.0f, inva);
    float oma  = 1.0f - a;
    float y = in[i];
    float x = (y > 0.0f) ? y : y * inva;
#pragma unroll
    for (int it = 0; it < 8; ++it) {
        float e  = __expf(-fabsf(x));
        float op = 1.0f + e;
        float sp = __logf(op) + fmaxf(x, 0.0f);
        float fx = fmaf(a, x, oma * sp);
        float num = (x >= 0.0f) ? fmaf(a, e, 1.0f) : (a + e);
        x -= __fdividef((fx - y) * op, num);
    }
    out[i] = x;
}

extern "C" void kernel_launch(void* const* d_in, const int* in_sizes, int n_in,
                              void* d_out, int out_size)
{
    const float* in        = (const float*)d_in[0];
    const float* raw_alpha = (const float*)d_in[1];
    float* out             = (float*)d_out;
    int n = in_sizes[0];

    build_table<<<(NSEG + 127) / 128, 128>>>(raw_alpha);

    int n4 = n / 4;
    if (n4 > 0) {
        int blocks = NBLOCKS;
        int needed = (n4 + TPB - 1) / TPB;
        if (needed < blocks) blocks = needed;
        inv_lsp_main<<<blocks, TPB>>>((const float4*)in, (float4*)out, n4);
    }
    int rem = n - n4 * 4;
    if (rem > 0) {
        inv_lsp_scalar_tail<<<1, 256>>>(in, out, n4 * 4, n);
    }
}